// round 14
// baseline (speedup 1.0000x reference)
#include <cuda_runtime.h>
#include <math.h>

#define BB 2
#define QQ 2048
#define FF 1538
#define CH 514          // faces per smem chunk (3 chunks cover 1538)

__device__ float g_res[BB * QQ];
__device__ float g_partial[BB];
__device__ unsigned int g_done = 0;

// ---------------------------------------------------------------------------
// fast helpers
// ---------------------------------------------------------------------------
__device__ __forceinline__ float sqrt_approx(float x) {
    float r; asm("sqrt.approx.f32 %0, %1;" : "=f"(r) : "f"(x)); return r;
}
__device__ __forceinline__ float rcp_approx(float x) {
    float r; asm("rcp.approx.f32 %0, %1;" : "=f"(r) : "f"(x)); return r;
}

// atan2 via quadrant folding + degree-11 odd minimax poly (|err| ~ 3e-6)
__device__ __forceinline__ float fast_atan2(float y, float x) {
    float ax = fabsf(x), ay = fabsf(y);
    float mx = fmaxf(ax, ay), mn = fminf(ax, ay);
    float t = mn * rcp_approx(mx);
    float s = t * t;
    float p =             -0.01172120f;
    p = fmaf(p, s,  0.05265332f);
    p = fmaf(p, s, -0.11643287f);
    p = fmaf(p, s,  0.19354346f);
    p = fmaf(p, s, -0.33262347f);
    p = fmaf(p, s,  0.99997726f);
    float r = p * t;
    if (ay > ax) r = 1.57079632679f - r;
    if (x < 0.0f) r = 3.14159265359f - r;
    return copysignf(r, y);
}

// face -> (num, den) of the half-solid-angle tangent (van Oosterom)
__device__ __forceinline__ void face_nd(const float4 v0, const float4 v1,
                                        const float4 v2,
                                        float px, float py, float pz,
                                        float& num, float& den) {
    float ax = v0.x - px, ay = v0.y - py, az = v0.z - pz;
    float bx = v0.w - px, by = v1.x - py, bz = v1.y - pz;
    float cx = v1.z - px, cy = v1.w - py, cz = v2.x - pz;

    float na = sqrt_approx(fmaf(ax, ax, fmaf(ay, ay, az * az)));
    float nb = sqrt_approx(fmaf(bx, bx, fmaf(by, by, bz * bz)));
    float nc = sqrt_approx(fmaf(cx, cx, fmaf(cy, cy, cz * cz)));

    float crx = by * cz - bz * cy;
    float cry = bz * cx - bx * cz;
    float crz = bx * cy - by * cx;

    num = fmaf(ax, crx, fmaf(ay, cry, az * crz));
    float d01 = fmaf(ax, bx, fmaf(ay, by, az * bz));
    float d12 = fmaf(bx, cx, fmaf(by, cy, bz * cz));
    float d02 = fmaf(ax, cx, fmaf(ay, cy, az * cz));

    den = fmaf(na * nb, nc, fmaf(d01, nc, fmaf(d02, nb, d12 * na)));
}

// merged angle for two faces: atan2(n1,d1)+atan2(n2,d2) with exact 2pi fixup
__device__ __forceinline__ float merged_atan(float n1, float d1,
                                             float n2, float d2) {
    float zx = fmaf(-n1, n2, d1 * d2);
    float zy = fmaf(n1, d2, n2 * d1);
    float t = fast_atan2(zy, zx);
    if (n1 > 0.0f && n2 > 0.0f && t < 0.0f) t += 6.28318530718f;
    if (n1 < 0.0f && n2 < 0.0f && t > 0.0f) t -= 6.28318530718f;
    return t;
}

// ---------------------------------------------------------------------------
// Kernel 1: winding numbers + residuals.
// TWO queries per warp (ILP=2), TWO warps per query pair (face split).
// Unroll-2 over faces with angle-sum merging (1 atan per 2 faces per query).
// 128-thread blocks, 4 queries/block -> 1024 blocks.
// ---------------------------------------------------------------------------
__global__ __launch_bounds__(128) void wn_kernel(const float* __restrict__ points,
                                                 const float* __restrict__ tris,
                                                 const float* __restrict__ occ) {
    __shared__ float st[CH * 12];
    __shared__ float sacc[8];     // [warp*2 + whichQuery]

    int tid  = threadIdx.x;
    int warp = tid >> 5;          // 0..3
    int lane = tid & 31;
    int pair = warp >> 1;         // query pair 0/1 within block
    int half = warp & 1;          // face-stride half

    int qA = blockIdx.x * 4 + pair * 2;   // 1024 blocks * 4 queries = 4096
    int qB = qA + 1;
    int b  = qA >> 11;                    // batch (uniform per block)

    float pxA = points[qA * 3 + 0], pyA = points[qA * 3 + 1], pzA = points[qA * 3 + 2];
    float pxB = points[qB * 3 + 0], pyB = points[qB * 3 + 1], pzB = points[qB * 3 + 2];

    const float* tb = tris + (size_t)b * FF * 9;

    float accA = 0.0f, accB = 0.0f;
    for (int base = 0; base < FF; base += CH) {
        int nf = min(CH, FF - base);
        __syncthreads();
        // stage: one face per thread, strided (no integer division)
        for (int f = tid; f < nf; f += 128) {
            const float* src = tb + (size_t)(base + f) * 9;
            float* dst = &st[f * 12];
            #pragma unroll
            for (int c = 0; c < 9; c++) dst[c] = src[c];
        }
        __syncthreads();

        int f = half * 32 + lane;
        // two faces in flight; merge their angles (one atan per query per pair)
        for (; f + 64 < nf; f += 128) {
            const float4* t4a = (const float4*)&st[f * 12];
            float4 u0 = t4a[0], u1 = t4a[1], u2 = t4a[2];
            const float4* t4b = (const float4*)&st[(f + 64) * 12];
            float4 w0 = t4b[0], w1 = t4b[1], w2 = t4b[2];

            float n1, d1, n2, d2;
            face_nd(u0, u1, u2, pxA, pyA, pzA, n1, d1);
            face_nd(w0, w1, w2, pxA, pyA, pzA, n2, d2);
            accA += merged_atan(n1, d1, n2, d2);

            float n3, d3, n4, d4;
            face_nd(u0, u1, u2, pxB, pyB, pzB, n3, d3);
            face_nd(w0, w1, w2, pxB, pyB, pzB, n4, d4);
            accB += merged_atan(n3, d3, n4, d4);
        }
        // remainder: single faces
        for (; f < nf; f += 64) {
            const float4* t4 = (const float4*)&st[f * 12];
            float4 v0 = t4[0], v1 = t4[1], v2 = t4[2];
            float n1, d1;
            face_nd(v0, v1, v2, pxA, pyA, pzA, n1, d1);
            accA += fast_atan2(n1, d1);
            float n2, d2;
            face_nd(v0, v1, v2, pxB, pyB, pzB, n2, d2);
            accB += fast_atan2(n2, d2);
        }
    }

    #pragma unroll
    for (int o = 16; o > 0; o >>= 1) {
        accA += __shfl_xor_sync(0xFFFFFFFFu, accA, o);
        accB += __shfl_xor_sync(0xFFFFFFFFu, accB, o);
    }

    if (lane == 0) {
        sacc[warp * 2 + 0] = accA;
        sacc[warp * 2 + 1] = accB;
    }
    __syncthreads();

    if (tid < 4) {  // tid = local query index 0..3
        int p    = tid >> 1;
        int qloc = tid & 1;
        float tot = sacc[(p * 2 + 0) * 2 + qloc] + sacc[(p * 2 + 1) * 2 + qloc];
        int q = blockIdx.x * 4 + tid;
        float wn = tot * 0.15915494309189535f;   // (2*atan2 sum)/(4*pi)
        g_res[q] = wn - occ[q];
    }
}

// ---------------------------------------------------------------------------
// Kernel 2: robust weighting (EXACT R6 version, proven ~10us).
// 1024 threads/batch; 8-bit radix-select + early small-select (<=64).
// ---------------------------------------------------------------------------
__device__ __forceinline__ unsigned int fkey(float f) {
    unsigned int u = __float_as_uint(f);
    return (u & 0x80000000u) ? ~u : (u | 0x80000000u);
}
__device__ __forceinline__ float key_to_float(unsigned int k) {
    unsigned int bits = (k & 0x80000000u) ? (k ^ 0x80000000u) : ~k;
    return __uint_as_float(bits);
}

struct SelShared {
    unsigned int hist[256];
    unsigned int wtot[8];
    unsigned int bc[3];      // bin, new k, bin count / result value
    unsigned int cand[64];
    unsigned int ccnt;
};

__device__ unsigned int radix_select(const unsigned int* keys, SelShared* ss,
                                     int tid, int k) {
    int wid  = tid >> 5;
    int lane = tid & 31;
    unsigned int prefix = 0;

    for (int shift = 24; shift >= 0; shift -= 8) {
        if (tid < 256) ss->hist[tid] = 0;
        if (tid == 0)  ss->ccnt = 0;
        __syncthreads();

        unsigned int hi = (shift == 24) ? 0u : (0xFFFFFFFFu << (shift + 8));
        #pragma unroll
        for (int i = tid; i < QQ; i += 1024) {
            unsigned int u = keys[i];
            if ((u & hi) == prefix) atomicAdd(&ss->hist[(u >> shift) & 255u], 1u);
        }
        __syncthreads();

        if (tid < 256) {
            unsigned int cnt = ss->hist[tid];
            unsigned int v   = cnt;
            #pragma unroll
            for (int o = 1; o < 32; o <<= 1) {
                unsigned int y = __shfl_up_sync(0xFFFFFFFFu, v, o);
                if (lane >= o) v += y;
            }
            if (lane == 31) ss->wtot[wid] = v;
            __syncthreads();

            if (wid == 0 && lane < 8) {
                unsigned int t0 = ss->wtot[lane];
                unsigned int t  = t0;
                #pragma unroll
                for (int o = 1; o < 8; o <<= 1) {
                    unsigned int y = __shfl_up_sync(0x000000FFu, t, o);
                    if (lane >= o) t += y;
                }
                ss->wtot[lane] = t - t0;
            }
            __syncthreads();

            unsigned int inc = v + ss->wtot[wid];
            unsigned int exc = inc - cnt;
            if ((int)exc <= k && k < (int)inc) {
                ss->bc[0] = (unsigned int)tid;
                ss->bc[1] = (unsigned int)(k - (int)exc);
                ss->bc[2] = cnt;
            }
        } else {
            __syncthreads();
            __syncthreads();
        }
        __syncthreads();

        prefix |= (ss->bc[0] << shift);
        k = (int)ss->bc[1];
        unsigned int cnt = ss->bc[2];

        if (shift > 0 && cnt <= 64u) {
            unsigned int hi2 = 0xFFFFFFFFu << shift;
            #pragma unroll
            for (int i = tid; i < QQ; i += 1024) {
                unsigned int u = keys[i];
                if ((u & hi2) == prefix) {
                    unsigned int p = atomicAdd(&ss->ccnt, 1u);
                    ss->cand[p] = u;
                }
            }
            __syncthreads();
            if (tid < 32) {
                int n = (int)cnt;
                for (int i = tid; i < n; i += 32) {
                    unsigned int v = ss->cand[i];
                    int less = 0, eq = 0;
                    for (int j = 0; j < n; j++) {
                        unsigned int u = ss->cand[j];
                        less += (u < v);
                        eq   += (u == v);
                    }
                    if (less <= k && k < less + eq) ss->bc[2] = v;
                }
            }
            __syncthreads();
            return ss->bc[2];
        }
        __syncthreads();
    }
    return prefix;
}

__global__ __launch_bounds__(1024) void robust_kernel(float* __restrict__ out) {
    __shared__ float        rs[QQ];
    __shared__ unsigned int keys[QQ];
    __shared__ SelShared    ss;
    __shared__ float        red[32];

    int b   = blockIdx.x;
    int tid = threadIdx.x;

    #pragma unroll
    for (int i = tid; i < QQ; i += 1024) {
        float v = g_res[b * QQ + i];
        rs[i]   = v;
        keys[i] = fkey(v);
    }
    __syncthreads();

    float med = key_to_float(radix_select(keys, &ss, tid, (QQ - 1) / 2));
    __syncthreads();

    #pragma unroll
    for (int i = tid; i < QQ; i += 1024)
        keys[i] = fkey(fabsf(rs[i] - med));
    __syncthreads();

    float mad = key_to_float(radix_select(keys, &ss, tid, (QQ - 1) / 2));

    float scale = (mad / 0.67449f) * 4.6851f;

    float sum = 0.0f;
    #pragma unroll
    for (int i = tid; i < QQ; i += 1024) {
        float r  = rs[i];
        float nr = r / scale;
        float t  = 1.0f - nr * nr;
        float w  = (nr >= 1.0f) ? 0.0f : t * t;
        sum += w * r * r;
    }

    #pragma unroll
    for (int o = 16; o > 0; o >>= 1)
        sum += __shfl_xor_sync(0xFFFFFFFFu, sum, o);
    if ((tid & 31) == 0) red[tid >> 5] = sum;
    __syncthreads();

    if (tid < 32) {
        float s = red[tid];
        #pragma unroll
        for (int o = 16; o > 0; o >>= 1)
            s += __shfl_xor_sync(0xFFFFFFFFu, s, o);
        if (tid == 0) {
            g_partial[b] = s;
            __threadfence();
            unsigned int prev = atomicAdd(&g_done, 1u);
            if (prev == BB - 1) {
                out[0] = 0.5f * (g_partial[0] + g_partial[1]);
                g_done = 0;  // reset for next graph replay
            }
        }
    }
}

extern "C" void kernel_launch(void* const* d_in, const int* in_sizes, int n_in,
                              void* d_out, int out_size) {
    const float* points = (const float*)d_in[0];  // (B,Q,3)
    const float* tris   = (const float*)d_in[1];  // (B,F,3,3)
    const float* occ    = (const float*)d_in[2];  // (B,Q)
    float* out = (float*)d_out;

    wn_kernel<<<(BB * QQ) / 4, 128>>>(points, tris, occ);
    robust_kernel<<<BB, 1024>>>(out);
}